// round 5
// baseline (speedup 1.0000x reference)
#include <cuda_runtime.h>
#include <cuda_bf16.h>

#define NN 50000
#define NE 640000
#define RK 128
#define NG 50
#define LN_EPS 1e-5f
#define CAP 96          // per-dst bucket capacity (max in-degree; Poisson(12.8))

// ---------------- zero-initialized prep block (single memset) ---------------
struct PrepZero {
    int cnt_in[NN];     // in-degree / bucket fill counters
    int deg_out[NN];
    int mark0[NN];
    int mark1[NN];
    int count0;
    int count1;
};
__device__ PrepZero g_z;

// ---------------- other scratch ---------------------------------------------
__device__ float g_h[NN * RK];       // post-GEMM features (UNscaled)
__device__ float g_bufA[NN * RK];    // feats1 (valid at N0 rows)
__device__ float g_bufB[NN * RK];    // feats2 (valid at N1 rows)
__device__ float g_inv_in[NN];
__device__ float g_inv_out[NN];
__device__ int   g_bucket[NN * CAP]; // src ids, bucketed by dst (19.2MB)
__device__ int   g_tgt[NG];
__device__ int   g_n0_list[NN];
__device__ int   g_n1_list[NN];

// ---------------- f32x2 helpers ---------------------------------------------
__device__ __forceinline__ unsigned long long pack2_dup(float x) {
    unsigned long long r;
    unsigned int u = __float_as_uint(x);
    asm("mov.b64 %0, {%1, %1};" : "=l"(r) : "r"(u));
    return r;
}
__device__ __forceinline__ unsigned long long fma2(unsigned long long a,
                                                   unsigned long long b,
                                                   unsigned long long c) {
    unsigned long long d;
    asm("fma.rn.f32x2 %0, %1, %2, %3;" : "=l"(d) : "l"(a), "l"(b), "l"(c));
    return d;
}
__device__ __forceinline__ void unpack2(unsigned long long v, float& a, float& b) {
    unsigned int lo, hi;
    asm("mov.b64 {%0, %1}, %2;" : "=r"(lo), "=r"(hi) : "l"(v));
    a = __uint_as_float(lo);
    b = __uint_as_float(hi);
}

// ---------------- single-pass bucket fill + degrees --------------------------
__global__ void fill_kernel(const int* __restrict__ src, const int* __restrict__ dst) {
    int i = (blockIdx.x * blockDim.x + threadIdx.x) * 4;
    if (i < NE) {
        int4 s4 = *(const int4*)(src + i);
        int4 d4 = *(const int4*)(dst + i);
        int ss[4] = {s4.x, s4.y, s4.z, s4.w};
        int dd[4] = {d4.x, d4.y, d4.z, d4.w};
        #pragma unroll
        for (int j = 0; j < 4; j++) {
            int slot = atomicAdd(&g_z.cnt_in[dd[j]], 1);
            if (slot < CAP) g_bucket[dd[j] * CAP + slot] = ss[j];
            atomicAdd(&g_z.deg_out[ss[j]], 1);
        }
    }
}

__global__ void inv_kernel() {
    int i = blockIdx.x * blockDim.x + threadIdx.x;
    if (i < NN) {
        g_inv_in[i]  = rsqrtf(fmaxf((float)g_z.cnt_in[i], 1.0f));
        g_inv_out[i] = rsqrtf(fmaxf((float)g_z.deg_out[i], 1.0f));
    }
}

// ---------------- frontier construction (bucket walks) -----------------------
// Single block: targets from batch_num_nodes, then N1 = srcs of their in-edges.
__global__ void frontier1_kernel(const int* __restrict__ bnn) {
    __shared__ int sb[NG];
    int tid = threadIdx.x, lane = tid & 31, wid = tid >> 5;
    if (tid < NG) sb[tid] = bnn[tid];
    __syncthreads();
    if (tid == 0) {
        int base = 0;
        for (int i = 0; i < NG; i++) { g_tgt[i] = base; base += sb[i]; }
    }
    __syncthreads();
    for (int t = wid; t < NG; t += blockDim.x >> 5) {
        int node = g_tgt[t];
        int cnt = min(g_z.cnt_in[node], CAP);
        for (int e = lane; e < cnt; e += 32) {
            int s = g_bucket[node * CAP + e];
            if (atomicExch(&g_z.mark1[s], 1) == 0) {
                int p = atomicAdd(&g_z.count1, 1);
                g_n1_list[p] = s;
            }
        }
    }
}

// N0 = srcs of in-edges of N1.
__global__ void frontier0_kernel() {
    int lane = threadIdx.x & 31;
    int w = (blockIdx.x * blockDim.x + threadIdx.x) >> 5;
    int nw = (gridDim.x * blockDim.x) >> 5;
    int cnt1 = g_z.count1;
    for (int i = w; i < cnt1; i += nw) {
        int node = g_n1_list[i];
        int cnt = min(g_z.cnt_in[node], CAP);
        for (int e = lane; e < cnt; e += 32) {
            int s = g_bucket[node * CAP + e];
            if (atomicExch(&g_z.mark0[s], 1) == 0) {
                int p = atomicAdd(&g_z.count0, 1);
                g_n0_list[p] = s;
            }
        }
    }
}

// ---------------- GEMM0: persistent, g_h = X @ W (unscaled) ------------------
#define GF_TILE 64
#define GF_SMEM (RK * RK * 4 + GF_TILE * RK * 8)  // W 64KB + dup'd A 64KB

__global__ void __launch_bounds__(256, 1)
gemm0_kernel(const float* __restrict__ X, const float* __restrict__ W) {
    extern __shared__ float sm[];
    float* Wsh = sm;                              // 128x128 floats
    float2* Ad = (float2*)(sm + RK * RK);         // 64 x 128 float2 (dup)
    const int tid = threadIdx.x;
    const int lane = tid & 31;
    const int wid = tid >> 5;

    {
        const float4* Wg = (const float4*)W;
        float4* Ws4 = (float4*)Wsh;
        #pragma unroll
        for (int j = 0; j < 16; j++) Ws4[tid + j * 256] = Wg[tid + j * 256];
    }

    const int ntiles = (NN + GF_TILE - 1) / GF_TILE;
    const int myrow = tid >> 5;
    const int kq = tid & 31;

    float4 pre[8];
    {
        int t0 = blockIdx.x;
        int rowBase = t0 * GF_TILE;
        #pragma unroll
        for (int j = 0; j < 8; j++) {
            int grow = rowBase + myrow + j * 8;
            pre[j] = make_float4(0.f, 0.f, 0.f, 0.f);
            if (t0 < ntiles && grow < NN)
                pre[j] = *(const float4*)(X + grow * RK + kq * 4);
        }
    }

    for (int t = blockIdx.x; t < ntiles; t += gridDim.x) {
        __syncthreads();
        #pragma unroll
        for (int j = 0; j < 8; j++) {
            float4 v = pre[j];
            float4* p4 = (float4*)(Ad + (myrow + j * 8) * RK + kq * 4);
            p4[0] = make_float4(v.x, v.x, v.y, v.y);
            p4[1] = make_float4(v.z, v.z, v.w, v.w);
        }
        __syncthreads();

        {
            int tn = t + gridDim.x;
            int rowBase = tn * GF_TILE;
            #pragma unroll
            for (int j = 0; j < 8; j++) {
                int grow = rowBase + myrow + j * 8;
                pre[j] = make_float4(0.f, 0.f, 0.f, 0.f);
                if (tn < ntiles && grow < NN)
                    pre[j] = *(const float4*)(X + grow * RK + kq * 4);
            }
        }

        unsigned long long acc[8][2];
        #pragma unroll
        for (int r = 0; r < 8; r++) { acc[r][0] = 0ULL; acc[r][1] = 0ULL; }

        const unsigned long long* Adu =
            (const unsigned long long*)(Ad + (wid * 8) * RK);

        #pragma unroll 4
        for (int k = 0; k < RK; k++) {
            ulonglong2 wv = *(const ulonglong2*)(Wsh + k * RK + lane * 4);
            #pragma unroll
            for (int r = 0; r < 8; r++) {
                unsigned long long av = Adu[r * RK + k];
                acc[r][0] = fma2(av, wv.x, acc[r][0]);
                acc[r][1] = fma2(av, wv.y, acc[r][1]);
            }
        }

        int rowBase = t * GF_TILE;
        #pragma unroll
        for (int r = 0; r < 8; r++) {
            int grow = rowBase + wid * 8 + r;
            if (grow < NN) {
                float x0, x1, x2, x3;
                unpack2(acc[r][0], x0, x1);
                unpack2(acc[r][1], x2, x3);
                *(float4*)(g_h + grow * RK + lane * 4) = make_float4(x0, x1, x2, x3);
            }
        }
    }
}

// ---------------- GEMM over indexed rows (layer 1), unscaled output ---------
#define GEMM_BM 64
#define ASH_STRIDE 129
#define GEMM_SMEM_BYTES ((RK * RK + GEMM_BM * ASH_STRIDE) * 4)

__global__ void __launch_bounds__(256, 2)
gemm_idx_kernel(const float* __restrict__ W) {
    extern __shared__ float sm[];
    float* Wsh = sm;
    float* Ash = sm + RK * RK;
    __shared__ int ridx[GEMM_BM];
    const int tid = threadIdx.x;

    {
        const float4* Wg = (const float4*)W;
        float4* Ws4 = (float4*)Wsh;
        #pragma unroll
        for (int j = 0; j < 16; j++) Ws4[tid + j * 256] = Wg[tid + j * 256];
    }

    int cnt = g_z.count0;
    int ntiles = (cnt + GEMM_BM - 1) / GEMM_BM;
    const int tr = tid >> 4;
    const int tc = tid & 15;

    for (int t = blockIdx.x; t < ntiles; t += gridDim.x) {
        __syncthreads();
        if (tid < GEMM_BM) {
            int gi = t * GEMM_BM + tid;
            ridx[tid] = (gi < cnt) ? g_n0_list[gi] : -1;
        }
        __syncthreads();
        #pragma unroll
        for (int j = 0; j < 8; j++) {
            int idx = tid + j * 256;
            int row = idx >> 5;
            int kq  = idx & 31;
            int gr = ridx[row];
            float4 v = make_float4(0.f, 0.f, 0.f, 0.f);
            if (gr >= 0) v = *(const float4*)(g_bufA + gr * RK + kq * 4);
            float* p = Ash + row * ASH_STRIDE + kq * 4;
            p[0] = v.x; p[1] = v.y; p[2] = v.z; p[3] = v.w;
        }
        __syncthreads();

        unsigned long long acc[4][4];
        #pragma unroll
        for (int r = 0; r < 4; r++)
            #pragma unroll
            for (int p = 0; p < 4; p++) acc[r][p] = 0ULL;

        const float* a0 = Ash + (tr * 4 + 0) * ASH_STRIDE;
        const float* a1 = Ash + (tr * 4 + 1) * ASH_STRIDE;
        const float* a2 = Ash + (tr * 4 + 2) * ASH_STRIDE;
        const float* a3 = Ash + (tr * 4 + 3) * ASH_STRIDE;
        const float* wbase = Wsh + tc * 8;

        #pragma unroll 4
        for (int k = 0; k < RK; k++) {
            ulonglong2 wA = *(const ulonglong2*)(wbase + k * RK);
            ulonglong2 wB = *(const ulonglong2*)(wbase + k * RK + 4);
            unsigned long long av0 = pack2_dup(a0[k]);
            unsigned long long av1 = pack2_dup(a1[k]);
            unsigned long long av2 = pack2_dup(a2[k]);
            unsigned long long av3 = pack2_dup(a3[k]);
            acc[0][0] = fma2(av0, wA.x, acc[0][0]);
            acc[0][1] = fma2(av0, wA.y, acc[0][1]);
            acc[0][2] = fma2(av0, wB.x, acc[0][2]);
            acc[0][3] = fma2(av0, wB.y, acc[0][3]);
            acc[1][0] = fma2(av1, wA.x, acc[1][0]);
            acc[1][1] = fma2(av1, wA.y, acc[1][1]);
            acc[1][2] = fma2(av1, wB.x, acc[1][2]);
            acc[1][3] = fma2(av1, wB.y, acc[1][3]);
            acc[2][0] = fma2(av2, wA.x, acc[2][0]);
            acc[2][1] = fma2(av2, wA.y, acc[2][1]);
            acc[2][2] = fma2(av2, wB.x, acc[2][2]);
            acc[2][3] = fma2(av2, wB.y, acc[2][3]);
            acc[3][0] = fma2(av3, wA.x, acc[3][0]);
            acc[3][1] = fma2(av3, wA.y, acc[3][1]);
            acc[3][2] = fma2(av3, wB.x, acc[3][2]);
            acc[3][3] = fma2(av3, wB.y, acc[3][3]);
        }

        #pragma unroll
        for (int r = 0; r < 4; r++) {
            int gr = ridx[tr * 4 + r];
            if (gr >= 0) {
                float x0, x1, x2, x3, x4, x5, x6, x7;
                unpack2(acc[r][0], x0, x1);
                unpack2(acc[r][1], x2, x3);
                unpack2(acc[r][2], x4, x5);
                unpack2(acc[r][3], x6, x7);
                *(float4*)(g_h + gr * RK + tc * 8)     = make_float4(x0, x1, x2, x3);
                *(float4*)(g_h + gr * RK + tc * 8 + 4) = make_float4(x4, x5, x6, x7);
            }
        }
    }
}

// ---------------- aggregation (inv_out applied at read) + LN + ReLU ---------
__device__ __forceinline__ void agg_node(int node, int lane, const float* b,
                                         const float* gamma, const float* beta,
                                         float* O) {
    int base = node * CAP;
    int deg = min(g_z.cnt_in[node], CAP);
    const float4* H4 = (const float4*)g_h;

    float ax = 0.f, ay = 0.f, az = 0.f, aw = 0.f;
    for (int eb = 0; eb < deg; eb += 32) {
        int cnt = min(32, deg - eb);
        int se = 0;
        float iov = 0.f;
        if (lane < cnt) {
            se = g_bucket[base + eb + lane];
            iov = g_inv_out[se];
        }
        for (int j = 0; j < cnt; j++) {
            int s = __shfl_sync(0xffffffffu, se, j);
            float io = __shfl_sync(0xffffffffu, iov, j);
            float4 v = H4[s * 32 + lane];
            ax = fmaf(v.x, io, ax);
            ay = fmaf(v.y, io, ay);
            az = fmaf(v.z, io, az);
            aw = fmaf(v.w, io, aw);
        }
    }

    float inv = g_inv_in[node];
    float4 bb = ((const float4*)b)[lane];
    float vx = ax * inv + bb.x;
    float vy = ay * inv + bb.y;
    float vz = az * inv + bb.z;
    float vw = aw * inv + bb.w;

    float sum = vx + vy + vz + vw;
    #pragma unroll
    for (int o = 16; o; o >>= 1) sum += __shfl_xor_sync(0xffffffffu, sum, o);
    float mean = sum * (1.0f / 128.0f);

    float cx = vx - mean, cy = vy - mean, cz = vz - mean, cw = vw - mean;
    float ss = cx * cx + cy * cy + cz * cz + cw * cw;
    #pragma unroll
    for (int o = 16; o; o >>= 1) ss += __shfl_xor_sync(0xffffffffu, ss, o);
    float rstd = rsqrtf(ss * (1.0f / 128.0f) + LN_EPS);

    float4 gm = ((const float4*)gamma)[lane];
    float4 bt = ((const float4*)beta)[lane];
    float4 o4;
    o4.x = fmaxf(cx * rstd * gm.x + bt.x, 0.f);
    o4.y = fmaxf(cy * rstd * gm.y + bt.y, 0.f);
    o4.z = fmaxf(cz * rstd * gm.z + bt.z, 0.f);
    o4.w = fmaxf(cw * rstd * gm.w + bt.w, 0.f);
    ((float4*)O)[node * 32 + lane] = o4;
}

__global__ void __launch_bounds__(256)
agg_idx_kernel(const float* __restrict__ b, const float* __restrict__ gamma,
               const float* __restrict__ beta, int level) {
    const int* list = level ? g_n1_list : g_n0_list;
    int cnt = level ? g_z.count1 : g_z.count0;
    float* O = level ? g_bufB : g_bufA;
    int lane = threadIdx.x & 31;
    int w = (blockIdx.x * blockDim.x + threadIdx.x) >> 5;
    int nw = (gridDim.x * blockDim.x) >> 5;
    for (int i = w; i < cnt; i += nw)
        agg_node(list[i], lane, b, gamma, beta, O);
}

// ---------------- final layer: per-target matvec + agg + LN -----------------
#define FINAL_SMEM_BYTES ((RK * RK + RK) * 4)
__global__ void __launch_bounds__(128)
final_kernel(const float* __restrict__ W, const float* __restrict__ b,
             const float* __restrict__ gamma, const float* __restrict__ beta,
             float* __restrict__ out) {
    extern __shared__ float sm[];
    float* Wsh = sm;
    float* xs  = sm + RK * RK;
    __shared__ float red[8];
    int t = threadIdx.x;
    int lane = t & 31, wid = t >> 5;

    {
        const float4* Wg = (const float4*)W;
        float4* Ws4 = (float4*)Wsh;
        #pragma unroll
        for (int j = 0; j < 32; j++) Ws4[t + j * 128] = Wg[t + j * 128];
    }

    int node = g_tgt[blockIdx.x];
    int base = node * CAP;
    int deg = min(g_z.cnt_in[node], CAP);
    float acc = 0.f;
    for (int e = 0; e < deg; e++) {
        int s = g_bucket[base + e];
        __syncthreads();
        xs[t] = g_bufB[s * RK + t] * g_inv_out[s];
        __syncthreads();
        float y = 0.f;
        #pragma unroll 16
        for (int k = 0; k < RK; k++) y += xs[k] * Wsh[k * RK + t];
        acc += y;
    }

    float v = acc * g_inv_in[node] + b[t];

    float sum = v;
    #pragma unroll
    for (int o = 16; o; o >>= 1) sum += __shfl_xor_sync(0xffffffffu, sum, o);
    if (lane == 0) red[wid] = sum;
    __syncthreads();
    float mean = (red[0] + red[1] + red[2] + red[3]) * (1.0f / 128.0f);

    float c = v - mean;
    float ss = c * c;
    #pragma unroll
    for (int o = 16; o; o >>= 1) ss += __shfl_xor_sync(0xffffffffu, ss, o);
    if (lane == 0) red[4 + wid] = ss;
    __syncthreads();
    float rstd = rsqrtf((red[4] + red[5] + red[6] + red[7]) * (1.0f / 128.0f) + LN_EPS);

    out[blockIdx.x * RK + t] = fmaxf(c * rstd * gamma[t] + beta[t], 0.f);
}

// ---------------- launch ----------------------------------------------------
extern "C" void kernel_launch(void* const* d_in, const int* in_sizes, int n_in,
                              void* d_out, int out_size) {
    const float* features = (const float*)d_in[0];
    const int*   src      = (const int*)d_in[1];
    const int*   dst      = (const int*)d_in[2];
    const int*   bnn      = (const int*)d_in[3];
    const float* Ws       = (const float*)d_in[4];
    const float* bs       = (const float*)d_in[5];
    const float* gammas   = (const float*)d_in[6];
    const float* betas    = (const float*)d_in[7];
    float* out = (float*)d_out;

    static cudaStream_t s_side = nullptr;
    static cudaEvent_t e_fork = nullptr, e_join = nullptr;
    if (!s_side) {
        cudaStreamCreateWithFlags(&s_side, cudaStreamNonBlocking);
        cudaEventCreateWithFlags(&e_fork, cudaEventDisableTiming);
        cudaEventCreateWithFlags(&e_join, cudaEventDisableTiming);
    }

    cudaFuncSetAttribute(gemm0_kernel, cudaFuncAttributeMaxDynamicSharedMemorySize,
                         GF_SMEM);
    cudaFuncSetAttribute(gemm_idx_kernel, cudaFuncAttributeMaxDynamicSharedMemorySize,
                         GEMM_SMEM_BYTES);
    cudaFuncSetAttribute(final_kernel, cudaFuncAttributeMaxDynamicSharedMemorySize,
                         FINAL_SMEM_BYTES);

    // --- side stream: layer-0 GEMM (independent of all graph prep) ----------
    cudaEventRecord(e_fork, 0);
    cudaStreamWaitEvent(s_side, e_fork, 0);
    gemm0_kernel<<<148, 256, GF_SMEM, s_side>>>(features, Ws);
    cudaEventRecord(e_join, s_side);

    // --- main stream: graph prep (one edge pass + tiny walks) ----------------
    void* zp = nullptr;
    cudaGetSymbolAddress(&zp, g_z);
    cudaMemsetAsync(zp, 0, sizeof(PrepZero), 0);

    fill_kernel<<<(NE / 4 + 255) / 256, 256>>>(src, dst);
    inv_kernel<<<(NN + 255) / 256, 256>>>();
    frontier1_kernel<<<1, 256>>>(bnn);
    frontier0_kernel<<<64, 256>>>();

    // --- join: aggregation needs g_h from gemm0 ------------------------------
    cudaStreamWaitEvent(0, e_join, 0);

    agg_idx_kernel<<<256, 256>>>(bs, gammas, betas, 0);
    gemm_idx_kernel<<<120, 256, GEMM_SMEM_BYTES>>>(Ws + RK * RK);
    agg_idx_kernel<<<64, 256>>>(bs + RK, gammas + RK, betas + RK, 1);
    final_kernel<<<NG, 128, FINAL_SMEM_BYTES>>>(Ws + 2 * RK * RK, bs + 2 * RK,
                                                gammas + 2 * RK, betas + 2 * RK, out);
}

// round 6
// speedup vs baseline: 1.0376x; 1.0376x over previous
#include <cuda_runtime.h>
#include <cuda_bf16.h>

#define NN 50000
#define NE 640000
#define RK 128
#define NG 50
#define LN_EPS 1e-5f
#define CAP 96          // per-dst bucket capacity (in-degree ~ Poisson(12.8))

// ---------------- zero-initialized prep block (single memset) ---------------
struct PrepZero {
    int cnt_in[NN];     // in-degree / bucket fill counters
    int deg_out[NN];
    int mark0[NN];
    int mark1[NN];
    int mtgt[NN];       // target bitmap
    int count0;
    int count1;
};
__device__ PrepZero g_z;

// ---------------- other scratch ---------------------------------------------
__device__ float g_h[NN * RK];       // post-GEMM features (UNscaled)
__device__ float g_bufA[NN * RK];    // feats1 (valid at N0 rows)
__device__ float g_bufB[NN * RK];    // feats2 (valid at N1 rows)
__device__ float g_inv_in[NN];
__device__ float g_inv_out[NN];
__device__ int   g_bucket[NN * CAP]; // src ids, bucketed by dst (19.2MB)
__device__ int   g_tgt[NG];
__device__ int   g_n0_list[NN];
__device__ int   g_n1_list[NN];

// ---------------- f32x2 helpers ---------------------------------------------
__device__ __forceinline__ unsigned long long pack2_dup(float x) {
    unsigned long long r;
    unsigned int u = __float_as_uint(x);
    asm("mov.b64 %0, {%1, %1};" : "=l"(r) : "r"(u));
    return r;
}
__device__ __forceinline__ unsigned long long fma2(unsigned long long a,
                                                   unsigned long long b,
                                                   unsigned long long c) {
    unsigned long long d;
    asm("fma.rn.f32x2 %0, %1, %2, %3;" : "=l"(d) : "l"(a), "l"(b), "l"(c));
    return d;
}
__device__ __forceinline__ void unpack2(unsigned long long v, float& a, float& b) {
    unsigned int lo, hi;
    asm("mov.b64 {%0, %1}, %2;" : "=r"(lo), "=r"(hi) : "l"(v));
    a = __uint_as_float(lo);
    b = __uint_as_float(hi);
}

// ---------------- targets init ----------------------------------------------
__global__ void tgt_init_kernel(const int* __restrict__ bnn) {
    __shared__ int sb[NG];
    int t = threadIdx.x;
    if (t < NG) sb[t] = bnn[t];
    __syncthreads();
    if (t == 0) {
        int base = 0;
        for (int i = 0; i < NG; i++) {
            g_tgt[i] = base;
            g_z.mtgt[base] = 1;
            base += sb[i];
        }
    }
}

// ---------------- single-pass: buckets + degrees + N1 ------------------------
__global__ void fill_kernel(const int* __restrict__ src, const int* __restrict__ dst) {
    int i = (blockIdx.x * blockDim.x + threadIdx.x) * 4;
    if (i < NE) {
        int4 s4 = *(const int4*)(src + i);
        int4 d4 = *(const int4*)(dst + i);
        int ss[4] = {s4.x, s4.y, s4.z, s4.w};
        int dd[4] = {d4.x, d4.y, d4.z, d4.w};
        #pragma unroll
        for (int j = 0; j < 4; j++) {
            int slot = atomicAdd(&g_z.cnt_in[dd[j]], 1);
            if (slot < CAP) g_bucket[dd[j] * CAP + slot] = ss[j];
            atomicAdd(&g_z.deg_out[ss[j]], 1);
            if (g_z.mtgt[dd[j]]) {
                if (atomicExch(&g_z.mark1[ss[j]], 1) == 0) {
                    int p = atomicAdd(&g_z.count1, 1);
                    g_n1_list[p] = ss[j];
                }
            }
        }
    }
}

// ---------------- N0 = in-neighbors of N1 (parallel bucket walk) -------------
__global__ void frontier0_kernel() {
    int lane = threadIdx.x & 31;
    int w = (blockIdx.x * blockDim.x + threadIdx.x) >> 5;
    int nw = (gridDim.x * blockDim.x) >> 5;
    int cnt1 = g_z.count1;
    for (int i = w; i < cnt1; i += nw) {
        int node = g_n1_list[i];
        int cnt = min(g_z.cnt_in[node], CAP);
        for (int e = lane; e < cnt; e += 32) {
            int s = g_bucket[node * CAP + e];
            if (atomicExch(&g_z.mark0[s], 1) == 0) {
                int p = atomicAdd(&g_z.count0, 1);
                g_n0_list[p] = s;
            }
        }
    }
}

__global__ void inv_kernel() {
    int i = blockIdx.x * blockDim.x + threadIdx.x;
    if (i < NN) {
        g_inv_in[i]  = rsqrtf(fmaxf((float)g_z.cnt_in[i], 1.0f));
        g_inv_out[i] = rsqrtf(fmaxf((float)g_z.deg_out[i], 1.0f));
    }
}

// ---------------- GEMM0: persistent, g_h = X @ W (unscaled) ------------------
#define GF_TILE 64
#define GF_SMEM (RK * RK * 4 + GF_TILE * RK * 8)  // W 64KB + dup'd A 64KB

__global__ void __launch_bounds__(256, 1)
gemm0_kernel(const float* __restrict__ X, const float* __restrict__ W) {
    extern __shared__ float sm[];
    float* Wsh = sm;                              // 128x128 floats
    float2* Ad = (float2*)(sm + RK * RK);         // 64 x 128 float2 (dup)
    const int tid = threadIdx.x;
    const int lane = tid & 31;
    const int wid = tid >> 5;

    {
        const float4* Wg = (const float4*)W;
        float4* Ws4 = (float4*)Wsh;
        #pragma unroll
        for (int j = 0; j < 16; j++) Ws4[tid + j * 256] = Wg[tid + j * 256];
    }

    const int ntiles = (NN + GF_TILE - 1) / GF_TILE;
    const int myrow = tid >> 5;
    const int kq = tid & 31;

    float4 pre[8];
    {
        int t0 = blockIdx.x;
        int rowBase = t0 * GF_TILE;
        #pragma unroll
        for (int j = 0; j < 8; j++) {
            int grow = rowBase + myrow + j * 8;
            pre[j] = make_float4(0.f, 0.f, 0.f, 0.f);
            if (t0 < ntiles && grow < NN)
                pre[j] = *(const float4*)(X + grow * RK + kq * 4);
        }
    }

    for (int t = blockIdx.x; t < ntiles; t += gridDim.x) {
        __syncthreads();
        #pragma unroll
        for (int j = 0; j < 8; j++) {
            float4 v = pre[j];
            float4* p4 = (float4*)(Ad + (myrow + j * 8) * RK + kq * 4);
            p4[0] = make_float4(v.x, v.x, v.y, v.y);
            p4[1] = make_float4(v.z, v.z, v.w, v.w);
        }
        __syncthreads();

        {
            int tn = t + gridDim.x;
            int rowBase = tn * GF_TILE;
            #pragma unroll
            for (int j = 0; j < 8; j++) {
                int grow = rowBase + myrow + j * 8;
                pre[j] = make_float4(0.f, 0.f, 0.f, 0.f);
                if (tn < ntiles && grow < NN)
                    pre[j] = *(const float4*)(X + grow * RK + kq * 4);
            }
        }

        unsigned long long acc[8][2];
        #pragma unroll
        for (int r = 0; r < 8; r++) { acc[r][0] = 0ULL; acc[r][1] = 0ULL; }

        const unsigned long long* Adu =
            (const unsigned long long*)(Ad + (wid * 8) * RK);

        #pragma unroll 4
        for (int k = 0; k < RK; k++) {
            ulonglong2 wv = *(const ulonglong2*)(Wsh + k * RK + lane * 4);
            #pragma unroll
            for (int r = 0; r < 8; r++) {
                unsigned long long av = Adu[r * RK + k];
                acc[r][0] = fma2(av, wv.x, acc[r][0]);
                acc[r][1] = fma2(av, wv.y, acc[r][1]);
            }
        }

        int rowBase = t * GF_TILE;
        #pragma unroll
        for (int r = 0; r < 8; r++) {
            int grow = rowBase + wid * 8 + r;
            if (grow < NN) {
                float x0, x1, x2, x3;
                unpack2(acc[r][0], x0, x1);
                unpack2(acc[r][1], x2, x3);
                *(float4*)(g_h + grow * RK + lane * 4) = make_float4(x0, x1, x2, x3);
            }
        }
    }
}

// ---------------- GEMM over indexed rows (layer 1), unscaled output ---------
#define GEMM_BM 64
#define ASH_STRIDE 129
#define GEMM_SMEM_BYTES ((RK * RK + GEMM_BM * ASH_STRIDE) * 4)

__global__ void __launch_bounds__(256, 2)
gemm_idx_kernel(const float* __restrict__ W) {
    extern __shared__ float sm[];
    float* Wsh = sm;
    float* Ash = sm + RK * RK;
    __shared__ int ridx[GEMM_BM];
    const int tid = threadIdx.x;

    {
        const float4* Wg = (const float4*)W;
        float4* Ws4 = (float4*)Wsh;
        #pragma unroll
        for (int j = 0; j < 16; j++) Ws4[tid + j * 256] = Wg[tid + j * 256];
    }

    int cnt = g_z.count0;
    int ntiles = (cnt + GEMM_BM - 1) / GEMM_BM;
    const int tr = tid >> 4;
    const int tc = tid & 15;

    for (int t = blockIdx.x; t < ntiles; t += gridDim.x) {
        __syncthreads();
        if (tid < GEMM_BM) {
            int gi = t * GEMM_BM + tid;
            ridx[tid] = (gi < cnt) ? g_n0_list[gi] : -1;
        }
        __syncthreads();
        #pragma unroll
        for (int j = 0; j < 8; j++) {
            int idx = tid + j * 256;
            int row = idx >> 5;
            int kq  = idx & 31;
            int gr = ridx[row];
            float4 v = make_float4(0.f, 0.f, 0.f, 0.f);
            if (gr >= 0) v = *(const float4*)(g_bufA + gr * RK + kq * 4);
            float* p = Ash + row * ASH_STRIDE + kq * 4;
            p[0] = v.x; p[1] = v.y; p[2] = v.z; p[3] = v.w;
        }
        __syncthreads();

        unsigned long long acc[4][4];
        #pragma unroll
        for (int r = 0; r < 4; r++)
            #pragma unroll
            for (int p = 0; p < 4; p++) acc[r][p] = 0ULL;

        const float* a0 = Ash + (tr * 4 + 0) * ASH_STRIDE;
        const float* a1 = Ash + (tr * 4 + 1) * ASH_STRIDE;
        const float* a2 = Ash + (tr * 4 + 2) * ASH_STRIDE;
        const float* a3 = Ash + (tr * 4 + 3) * ASH_STRIDE;
        const float* wbase = Wsh + tc * 8;

        #pragma unroll 4
        for (int k = 0; k < RK; k++) {
            ulonglong2 wA = *(const ulonglong2*)(wbase + k * RK);
            ulonglong2 wB = *(const ulonglong2*)(wbase + k * RK + 4);
            unsigned long long av0 = pack2_dup(a0[k]);
            unsigned long long av1 = pack2_dup(a1[k]);
            unsigned long long av2 = pack2_dup(a2[k]);
            unsigned long long av3 = pack2_dup(a3[k]);
            acc[0][0] = fma2(av0, wA.x, acc[0][0]);
            acc[0][1] = fma2(av0, wA.y, acc[0][1]);
            acc[0][2] = fma2(av0, wB.x, acc[0][2]);
            acc[0][3] = fma2(av0, wB.y, acc[0][3]);
            acc[1][0] = fma2(av1, wA.x, acc[1][0]);
            acc[1][1] = fma2(av1, wA.y, acc[1][1]);
            acc[1][2] = fma2(av1, wB.x, acc[1][2]);
            acc[1][3] = fma2(av1, wB.y, acc[1][3]);
            acc[2][0] = fma2(av2, wA.x, acc[2][0]);
            acc[2][1] = fma2(av2, wA.y, acc[2][1]);
            acc[2][2] = fma2(av2, wB.x, acc[2][2]);
            acc[2][3] = fma2(av2, wB.y, acc[2][3]);
            acc[3][0] = fma2(av3, wA.x, acc[3][0]);
            acc[3][1] = fma2(av3, wA.y, acc[3][1]);
            acc[3][2] = fma2(av3, wB.x, acc[3][2]);
            acc[3][3] = fma2(av3, wB.y, acc[3][3]);
        }

        #pragma unroll
        for (int r = 0; r < 4; r++) {
            int gr = ridx[tr * 4 + r];
            if (gr >= 0) {
                float x0, x1, x2, x3, x4, x5, x6, x7;
                unpack2(acc[r][0], x0, x1);
                unpack2(acc[r][1], x2, x3);
                unpack2(acc[r][2], x4, x5);
                unpack2(acc[r][3], x6, x7);
                *(float4*)(g_h + gr * RK + tc * 8)     = make_float4(x0, x1, x2, x3);
                *(float4*)(g_h + gr * RK + tc * 8 + 4) = make_float4(x4, x5, x6, x7);
            }
        }
    }
}

// ---------------- aggregation (inv_out applied at read) + LN + ReLU ---------
__device__ __forceinline__ void agg_node(int node, int lane, const float* b,
                                         const float* gamma, const float* beta,
                                         float* O) {
    int base = node * CAP;
    int deg = min(g_z.cnt_in[node], CAP);
    const float4* H4 = (const float4*)g_h;

    float ax = 0.f, ay = 0.f, az = 0.f, aw = 0.f;
    for (int eb = 0; eb < deg; eb += 32) {
        int cnt = min(32, deg - eb);
        int se = 0;
        float iov = 0.f;
        if (lane < cnt) {
            se = g_bucket[base + eb + lane];
            iov = g_inv_out[se];
        }
        for (int j = 0; j < cnt; j++) {
            int s = __shfl_sync(0xffffffffu, se, j);
            float io = __shfl_sync(0xffffffffu, iov, j);
            float4 v = H4[s * 32 + lane];
            ax = fmaf(v.x, io, ax);
            ay = fmaf(v.y, io, ay);
            az = fmaf(v.z, io, az);
            aw = fmaf(v.w, io, aw);
        }
    }

    float inv = g_inv_in[node];
    float4 bb = ((const float4*)b)[lane];
    float vx = ax * inv + bb.x;
    float vy = ay * inv + bb.y;
    float vz = az * inv + bb.z;
    float vw = aw * inv + bb.w;

    float sum = vx + vy + vz + vw;
    #pragma unroll
    for (int o = 16; o; o >>= 1) sum += __shfl_xor_sync(0xffffffffu, sum, o);
    float mean = sum * (1.0f / 128.0f);

    float cx = vx - mean, cy = vy - mean, cz = vz - mean, cw = vw - mean;
    float ss = cx * cx + cy * cy + cz * cz + cw * cw;
    #pragma unroll
    for (int o = 16; o; o >>= 1) ss += __shfl_xor_sync(0xffffffffu, ss, o);
    float rstd = rsqrtf(ss * (1.0f / 128.0f) + LN_EPS);

    float4 gm = ((const float4*)gamma)[lane];
    float4 bt = ((const float4*)beta)[lane];
    float4 o4;
    o4.x = fmaxf(cx * rstd * gm.x + bt.x, 0.f);
    o4.y = fmaxf(cy * rstd * gm.y + bt.y, 0.f);
    o4.z = fmaxf(cz * rstd * gm.z + bt.z, 0.f);
    o4.w = fmaxf(cw * rstd * gm.w + bt.w, 0.f);
    ((float4*)O)[node * 32 + lane] = o4;
}

__global__ void __launch_bounds__(256)
agg_idx_kernel(const float* __restrict__ b, const float* __restrict__ gamma,
               const float* __restrict__ beta, int level) {
    const int* list = level ? g_n1_list : g_n0_list;
    int cnt = level ? g_z.count1 : g_z.count0;
    float* O = level ? g_bufB : g_bufA;
    int lane = threadIdx.x & 31;
    int w = (blockIdx.x * blockDim.x + threadIdx.x) >> 5;
    int nw = (gridDim.x * blockDim.x) >> 5;
    for (int i = w; i < cnt; i += nw)
        agg_node(list[i], lane, b, gamma, beta, O);
}

// ---------------- final layer: per-target matvec + agg + LN -----------------
#define FINAL_SMEM_BYTES ((RK * RK + RK) * 4)
__global__ void __launch_bounds__(128)
final_kernel(const float* __restrict__ W, const float* __restrict__ b,
             const float* __restrict__ gamma, const float* __restrict__ beta,
             float* __restrict__ out) {
    extern __shared__ float sm[];
    float* Wsh = sm;
    float* xs  = sm + RK * RK;
    __shared__ float red[8];
    int t = threadIdx.x;
    int lane = t & 31, wid = t >> 5;

    {
        const float4* Wg = (const float4*)W;
        float4* Ws4 = (float4*)Wsh;
        #pragma unroll
        for (int j = 0; j < 32; j++) Ws4[t + j * 128] = Wg[t + j * 128];
    }

    int node = g_tgt[blockIdx.x];
    int base = node * CAP;
    int deg = min(g_z.cnt_in[node], CAP);
    float acc = 0.f;
    for (int e = 0; e < deg; e++) {
        int s = g_bucket[base + e];
        __syncthreads();
        xs[t] = g_bufB[s * RK + t] * g_inv_out[s];
        __syncthreads();
        float y = 0.f;
        #pragma unroll 16
        for (int k = 0; k < RK; k++) y += xs[k] * Wsh[k * RK + t];
        acc += y;
    }

    float v = acc * g_inv_in[node] + b[t];

    float sum = v;
    #pragma unroll
    for (int o = 16; o; o >>= 1) sum += __shfl_xor_sync(0xffffffffu, sum, o);
    if (lane == 0) red[wid] = sum;
    __syncthreads();
    float mean = (red[0] + red[1] + red[2] + red[3]) * (1.0f / 128.0f);

    float c = v - mean;
    float ss = c * c;
    #pragma unroll
    for (int o = 16; o; o >>= 1) ss += __shfl_xor_sync(0xffffffffu, ss, o);
    if (lane == 0) red[4 + wid] = ss;
    __syncthreads();
    float rstd = rsqrtf((red[4] + red[5] + red[6] + red[7]) * (1.0f / 128.0f) + LN_EPS);

    out[blockIdx.x * RK + t] = fmaxf(c * rstd * gamma[t] + beta[t], 0.f);
}

// ---------------- launch ----------------------------------------------------
extern "C" void kernel_launch(void* const* d_in, const int* in_sizes, int n_in,
                              void* d_out, int out_size) {
    const float* features = (const float*)d_in[0];
    const int*   src      = (const int*)d_in[1];
    const int*   dst      = (const int*)d_in[2];
    const int*   bnn      = (const int*)d_in[3];
    const float* Ws       = (const float*)d_in[4];
    const float* bs       = (const float*)d_in[5];
    const float* gammas   = (const float*)d_in[6];
    const float* betas    = (const float*)d_in[7];
    float* out = (float*)d_out;

    static cudaStream_t s_side = nullptr;
    static cudaEvent_t e_fork = nullptr, e_join = nullptr;
    if (!s_side) {
        cudaStreamCreateWithFlags(&s_side, cudaStreamNonBlocking);
        cudaEventCreateWithFlags(&e_fork, cudaEventDisableTiming);
        cudaEventCreateWithFlags(&e_join, cudaEventDisableTiming);
    }

    cudaFuncSetAttribute(gemm0_kernel, cudaFuncAttributeMaxDynamicSharedMemorySize,
                         GF_SMEM);
    cudaFuncSetAttribute(gemm_idx_kernel, cudaFuncAttributeMaxDynamicSharedMemorySize,
                         GEMM_SMEM_BYTES);
    cudaFuncSetAttribute(final_kernel, cudaFuncAttributeMaxDynamicSharedMemorySize,
                         FINAL_SMEM_BYTES);

    // --- side stream: layer-0 GEMM (independent of all graph prep) ----------
    cudaEventRecord(e_fork, 0);
    cudaStreamWaitEvent(s_side, e_fork, 0);
    gemm0_kernel<<<148, 256, GF_SMEM, s_side>>>(features, Ws);
    cudaEventRecord(e_join, s_side);

    // --- main stream: graph prep (one edge pass + short walks) ---------------
    void* zp = nullptr;
    cudaGetSymbolAddress(&zp, g_z);
    cudaMemsetAsync(zp, 0, sizeof(PrepZero), 0);

    tgt_init_kernel<<<1, 64>>>(bnn);
    fill_kernel<<<(NE / 4 + 255) / 256, 256>>>(src, dst);
    frontier0_kernel<<<128, 256>>>();
    inv_kernel<<<(NN + 255) / 256, 256>>>();

    // --- join: aggregation needs g_h from gemm0 ------------------------------
    cudaStreamWaitEvent(0, e_join, 0);

    agg_idx_kernel<<<256, 256>>>(bs, gammas, betas, 0);
    gemm_idx_kernel<<<120, 256, GEMM_SMEM_BYTES>>>(Ws + RK * RK);
    agg_idx_kernel<<<64, 256>>>(bs + RK, gammas + RK, betas + RK, 1);
    final_kernel<<<NG, 128, FINAL_SMEM_BYTES>>>(Ws + 2 * RK * RK, bs + 2 * RK,
                                                gammas + 2 * RK, betas + 2 * RK, out);
}